// round 2
// baseline (speedup 1.0000x reference)
#include <cuda_runtime.h>
#include <cuda_bf16.h>

// Problem constants
#define B   256
#define T   1024
#define H   128
#define I   19
#define BT  (B*T)            // 262144
#define NEL (BT*H)           // 33554432

// Scratch (device globals: allocation-free per harness rules)
__device__ float g_buf0[NEL];   // pre-activations (layer0 then layer1)
__device__ float g_buf1[NEL];   // layer-0 hidden outputs

typedef unsigned long long u64;

__device__ __forceinline__ u64 fma2(u64 a, u64 b, u64 c) {
    u64 d;
    asm("fma.rn.f32x2 %0, %1, %2, %3;" : "=l"(d) : "l"(a), "l"(b), "l"(c));
    return d;
}
__device__ __forceinline__ u64 add2(u64 a, u64 b) {
    u64 d;
    asm("add.rn.f32x2 %0, %1, %2;" : "=l"(d) : "l"(a), "l"(b));
    return d;
}
__device__ __forceinline__ float red2(u64 a) {
    float x, y;
    asm("mov.b64 {%0, %1}, %2;" : "=f"(x), "=f"(y) : "l"(a));
    return x + y;
}

// tanh(x) = 1 - 2/(1 + e^{2x}); ex2/rcp approx -> ~1e-7 abs err.
__device__ __forceinline__ float fast_tanh(float x) {
    float e, r;
    asm("ex2.approx.f32 %0, %1;" : "=f"(e) : "f"(x * 2.8853900817779268f));
    asm("rcp.approx.f32 %0, %1;" : "=f"(r) : "f"(e + 1.0f));
    return fmaf(-2.0f, r, 1.0f);
}

// ---------------------------------------------------------------------------
// Kernel 1: pre0[bt, j] = x[bt, :19] . W_ih0[j, :19] + b_ih0[j] + b_hh0[j]
// ---------------------------------------------------------------------------
__global__ void pre0_kernel(const float* __restrict__ x,
                            const float* __restrict__ W,
                            const float* __restrict__ bi,
                            const float* __restrict__ bh) {
    int idx = blockIdx.x * 256 + threadIdx.x;
    int j  = idx & (H - 1);
    int bt = idx >> 7;
    const float* xr = x + bt * I;
    const float* wr = W + j * I;
    float acc = __ldg(bi + j) + __ldg(bh + j);
#pragma unroll
    for (int f = 0; f < I; f++)
        acc = fmaf(__ldg(xr + f), __ldg(wr + f), acc);
    g_buf0[idx] = acc;
}

// ---------------------------------------------------------------------------
// Kernel 2: recurrent scan, split-K over thread pairs.
// 256 threads/CTA, one CTA per batch row. Lane pair (2m, 2m+1) of warp w
// handles output unit j = w*16 + m; even lane does k in [0,64), odd lane
// k in [64,128). Partials combined with shfl.xor(1). Even lane stores h to
// the (double-buffered, padded) shared h vector; odd lane does the global
// store. One __syncthreads per step. 4 warps/SMSP at 2 CTAs/SM.
// Shared halves are offset by 68 floats so the two broadcast addresses of
// each LDS.128 hit disjoint bank quads (272B -> +4 banks): conflict-free.
// ---------------------------------------------------------------------------
#define PAD_HALF 68

__global__ void __launch_bounds__(256, 2)
scan_kernel(int layer, const float* __restrict__ W, float* __restrict__ dout) {
    __shared__ __align__(16) float hbuf[2][136];
    const int tid  = threadIdx.x;
    const int l    = tid & 31;
    const int w    = tid >> 5;
    const int j    = (w << 4) + (l >> 1);
    const int half = l & 1;
    const int b    = blockIdx.x;

    const float* __restrict__ pre = g_buf0;
    float* __restrict__ out = (layer == 0) ? g_buf1 : dout;

    // This thread's half of W_hh row j: 32 packed f32x2 pairs.
    u64 wp[32];
    const u64* wrow = reinterpret_cast<const u64*>(W + j * H + (half << 6));
#pragma unroll
    for (int i = 0; i < 32; i++) wp[i] = __ldg(wrow + i);

    const int pos = (j < 64) ? j : (PAD_HALF + j - 64);
    if (!half) { hbuf[0][pos] = 0.0f; }
    __syncthreads();

    const int base = b * (T * H) + j;
    float p = __ldg(pre + base);

#pragma unroll 2
    for (int t = 0; t < T; t++) {
        int tn = (t + 1 < T) ? (t + 1) : t;
        float pn = __ldg(pre + base + tn * H);

        const ulonglong2* hp = reinterpret_cast<const ulonglong2*>(
            hbuf[t & 1] + (half ? PAD_HALF : 0));
        u64 a0 = 0, a1 = 0, a2 = 0, a3 = 0;
#pragma unroll
        for (int i = 0; i < 16; i += 2) {
            ulonglong2 q0 = hp[i];
            ulonglong2 q1 = hp[i + 1];
            a0 = fma2(wp[2 * i + 0], q0.x, a0);
            a1 = fma2(wp[2 * i + 1], q0.y, a1);
            a2 = fma2(wp[2 * i + 2], q1.x, a2);
            a3 = fma2(wp[2 * i + 3], q1.y, a3);
        }
        float s = red2(add2(add2(a0, a2), add2(a1, a3)));
        float o = __shfl_xor_sync(0xffffffffu, s, 1);
        float h = fast_tanh(s + o + p);

        if (!half) hbuf[(t & 1) ^ 1][pos] = h;   // even lane: shared update
        else       out[base + t * H]     = h;    // odd lane: global store
        p = pn;
        __syncthreads();
    }
}

// ---------------------------------------------------------------------------
// Kernel 3: layer-1 input projection, software-pipelined.
// 4-row tiles, double-buffered shared, register prefetch of the next tile
// issued immediately after the single per-tile __syncthreads so the global
// load latency overlaps ~770 cycles of fma issue.
// ---------------------------------------------------------------------------
#define PROJ_BLOCKS 512
#define PROJ_ROWS   (BT / PROJ_BLOCKS)   // 512 rows per block

__global__ void __launch_bounds__(128, 2)
proj_kernel(const float* __restrict__ W,
            const float* __restrict__ bi,
            const float* __restrict__ bh) {
    __shared__ __align__(16) float sh[2][4][128];
    const int j = threadIdx.x;

    u64 wp[64];
    const u64* wrow = reinterpret_cast<const u64*>(W + j * H);
#pragma unroll
    for (int i = 0; i < 64; i++) wp[i] = __ldg(wrow + i);

    const float bias = __ldg(bi + j) + __ldg(bh + j);
    const int rbeg = blockIdx.x * PROJ_ROWS;
    const int rend = rbeg + PROJ_ROWS;

    float r4[4];
#pragma unroll
    for (int i = 0; i < 4; i++) r4[i] = g_buf1[(rbeg + i) * H + j];

    int pbuf = 0;
#pragma unroll 1
    for (int r = rbeg; r < rend; r += 4) {
#pragma unroll
        for (int i = 0; i < 4; i++) sh[pbuf][i][j] = r4[i];
        __syncthreads();

        int rn = r + 4;
        if (rn < rend) {
#pragma unroll
            for (int i = 0; i < 4; i++) r4[i] = g_buf1[(rn + i) * H + j];
        }

#pragma unroll
        for (int i = 0; i < 4; i++) {
            const ulonglong2* hp = reinterpret_cast<const ulonglong2*>(sh[pbuf][i]);
            u64 a0 = 0, a1 = 0, a2 = 0, a3 = 0;
#pragma unroll
            for (int q = 0; q < 32; q += 2) {
                ulonglong2 x0 = hp[q];
                ulonglong2 x1 = hp[q + 1];
                a0 = fma2(wp[2 * q + 0], x0.x, a0);
                a1 = fma2(wp[2 * q + 1], x0.y, a1);
                a2 = fma2(wp[2 * q + 2], x1.x, a2);
                a3 = fma2(wp[2 * q + 3], x1.y, a3);
            }
            g_buf0[(r + i) * H + j] = bias + red2(add2(add2(a0, a2), add2(a1, a3)));
        }
        pbuf ^= 1;
    }
}

// ---------------------------------------------------------------------------
extern "C" void kernel_launch(void* const* d_in, const int* in_sizes, int n_in,
                              void* d_out, int out_size) {
    const float* x     = (const float*)d_in[0];
    const float* W_ih0 = (const float*)d_in[1];
    const float* W_hh0 = (const float*)d_in[2];
    const float* b_ih0 = (const float*)d_in[3];
    const float* b_hh0 = (const float*)d_in[4];
    const float* W_ih1 = (const float*)d_in[5];
    const float* W_hh1 = (const float*)d_in[6];
    const float* b_ih1 = (const float*)d_in[7];
    const float* b_hh1 = (const float*)d_in[8];
    float* out = (float*)d_out;

    // Layer 0 input projection -> g_buf0
    pre0_kernel<<<NEL / 256, 256>>>(x, W_ih0, b_ih0, b_hh0);
    // Layer 0 scan: g_buf0 -> g_buf1
    scan_kernel<<<B, 256>>>(0, W_hh0, out);
    // Layer 1 input projection: g_buf1 -> g_buf0
    proj_kernel<<<PROJ_BLOCKS, 128>>>(W_ih1, b_ih1, b_hh1);
    // Layer 1 scan: g_buf0 -> out
    scan_kernel<<<B, 256>>>(1, W_hh1, out);
}

// round 3
// speedup vs baseline: 1.1191x; 1.1191x over previous
#include <cuda_runtime.h>
#include <cuda_bf16.h>

// Problem constants
#define B   256
#define T   1024
#define H   128
#define I   19
#define BT  (B*T)            // 262144
#define NEL (BT*H)           // 33554432

// Scratch (device globals: allocation-free per harness rules)
__device__ float g_buf0[NEL];   // pre-activations (layer0 then layer1)
__device__ float g_buf1[NEL];   // layer-0 hidden outputs

typedef unsigned long long u64;

__device__ __forceinline__ u64 fma2(u64 a, u64 b, u64 c) {
    u64 d;
    asm("fma.rn.f32x2 %0, %1, %2, %3;" : "=l"(d) : "l"(a), "l"(b), "l"(c));
    return d;
}
__device__ __forceinline__ u64 add2(u64 a, u64 b) {
    u64 d;
    asm("add.rn.f32x2 %0, %1, %2;" : "=l"(d) : "l"(a), "l"(b));
    return d;
}
__device__ __forceinline__ float red2(u64 a) {
    float x, y;
    asm("mov.b64 {%0, %1}, %2;" : "=f"(x), "=f"(y) : "l"(a));
    return x + y;
}

// Single-MUFU tanh (sm_75+). ~1e-5 abs error, far under the 1e-3 gate.
__device__ __forceinline__ float fast_tanh(float x) {
    float r;
    asm("tanh.approx.f32 %0, %1;" : "=f"(r) : "f"(x));
    return r;
}

// ---------------------------------------------------------------------------
// Kernel 1: pre0[bt, j] = x[bt, :19] . W_ih0[j, :19] + b_ih0[j] + b_hh0[j]
// ---------------------------------------------------------------------------
__global__ void pre0_kernel(const float* __restrict__ x,
                            const float* __restrict__ W,
                            const float* __restrict__ bi,
                            const float* __restrict__ bh) {
    int idx = blockIdx.x * 256 + threadIdx.x;
    int j  = idx & (H - 1);
    int bt = idx >> 7;
    const float* xr = x + bt * I;
    const float* wr = W + j * I;
    float acc = __ldg(bi + j) + __ldg(bh + j);
#pragma unroll
    for (int f = 0; f < I; f++)
        acc = fmaf(__ldg(xr + f), __ldg(wr + f), acc);
    g_buf0[idx] = acc;
}

// ---------------------------------------------------------------------------
// Kernel 2: recurrent scan. One CTA (128 thr) per batch row; thread j owns
// output unit j with W_hh row j in 64 packed f32x2 registers. h double-
// buffered in shared, one __syncthreads per step.
// KEY FIX vs rounds 1-2: 4-deep register prefetch pipeline for the
// pre-activation stream, so the DRAM load latency (~1 step) no longer pins
// the step time (slack is now ~4 steps).
// ---------------------------------------------------------------------------
#define PF 4

__global__ void __launch_bounds__(128, 2)
scan_kernel(int layer, const float* __restrict__ W, float* __restrict__ dout) {
    __shared__ __align__(16) float hbuf[2][H];
    const int j = threadIdx.x;
    const int b = blockIdx.x;

    const float* __restrict__ pre = g_buf0;
    float* __restrict__ out = (layer == 0) ? g_buf1 : dout;

    // W_hh row j as 64 packed f32x2 pairs.
    u64 wp[64];
    const u64* wrow = reinterpret_cast<const u64*>(W + j * H);
#pragma unroll
    for (int i = 0; i < 64; i++) wp[i] = __ldg(wrow + i);

    hbuf[0][j] = 0.0f;

    const int base = b * (T * H) + j;

    // Prime the 4-deep pre-activation pipeline.
    float pf[PF];
#pragma unroll
    for (int i = 0; i < PF; i++) pf[i] = __ldg(pre + base + i * H);

    __syncthreads();

#pragma unroll 1
    for (int t = 0; t < T; t++) {
        float p = pf[t & (PF - 1)];
        int tn = (t + PF < T) ? (t + PF) : (T - 1);
        pf[t & (PF - 1)] = __ldg(pre + base + tn * H);   // consumed in 4 steps

        const ulonglong2* hp = reinterpret_cast<const ulonglong2*>(hbuf[t & 1]);
        u64 a0 = 0, a1 = 0, a2 = 0, a3 = 0;
#pragma unroll
        for (int i = 0; i < 32; i += 2) {
            ulonglong2 h0 = hp[i];
            ulonglong2 h1 = hp[i + 1];
            a0 = fma2(wp[2 * i + 0], h0.x, a0);
            a1 = fma2(wp[2 * i + 1], h0.y, a1);
            a2 = fma2(wp[2 * i + 2], h1.x, a2);
            a3 = fma2(wp[2 * i + 3], h1.y, a3);
        }
        float h = fast_tanh(p + red2(add2(add2(a0, a2), add2(a1, a3))));

        hbuf[(t & 1) ^ 1][j] = h;
        out[base + t * H] = h;
        __syncthreads();
    }
}

// ---------------------------------------------------------------------------
// Kernel 3: layer-1 input projection, software-pipelined with 8-row tiles so
// per-tile compute (~1100 cyc) covers the DRAM latency of the next tile's
// register prefetch. Double-buffered shared; one __syncthreads per tile side.
// ---------------------------------------------------------------------------
#define PROJ_BLOCKS 512
#define PROJ_ROWS   (BT / PROJ_BLOCKS)   // 512 rows per block
#define TILE        8

__global__ void __launch_bounds__(128, 2)
proj_kernel(const float* __restrict__ W,
            const float* __restrict__ bi,
            const float* __restrict__ bh) {
    __shared__ __align__(16) float sh[2][TILE][H];
    const int j = threadIdx.x;

    u64 wp[64];
    const u64* wrow = reinterpret_cast<const u64*>(W + j * H);
#pragma unroll
    for (int i = 0; i < 64; i++) wp[i] = __ldg(wrow + i);

    const float bias = __ldg(bi + j) + __ldg(bh + j);
    const int rbeg = blockIdx.x * PROJ_ROWS;
    const int rend = rbeg + PROJ_ROWS;

    float rt[TILE];
#pragma unroll
    for (int i = 0; i < TILE; i++) rt[i] = g_buf1[(rbeg + i) * H + j];

    int pbuf = 0;
#pragma unroll 1
    for (int r = rbeg; r < rend; r += TILE) {
#pragma unroll
        for (int i = 0; i < TILE; i++) sh[pbuf][i][j] = rt[i];
        __syncthreads();

        int rn = r + TILE;
        if (rn < rend) {
#pragma unroll
            for (int i = 0; i < TILE; i++) rt[i] = g_buf1[(rn + i) * H + j];
        }

#pragma unroll
        for (int i = 0; i < TILE; i++) {
            const ulonglong2* hp = reinterpret_cast<const ulonglong2*>(sh[pbuf][i]);
            u64 a0 = 0, a1 = 0, a2 = 0, a3 = 0;
#pragma unroll
            for (int q = 0; q < 32; q += 2) {
                ulonglong2 x0 = hp[q];
                ulonglong2 x1 = hp[q + 1];
                a0 = fma2(wp[2 * q + 0], x0.x, a0);
                a1 = fma2(wp[2 * q + 1], x0.y, a1);
                a2 = fma2(wp[2 * q + 2], x1.x, a2);
                a3 = fma2(wp[2 * q + 3], x1.y, a3);
            }
            g_buf0[(r + i) * H + j] = bias + red2(add2(add2(a0, a2), add2(a1, a3)));
        }
        __syncthreads();
        pbuf ^= 1;
    }
}

// ---------------------------------------------------------------------------
extern "C" void kernel_launch(void* const* d_in, const int* in_sizes, int n_in,
                              void* d_out, int out_size) {
    const float* x     = (const float*)d_in[0];
    const float* W_ih0 = (const float*)d_in[1];
    const float* W_hh0 = (const float*)d_in[2];
    const float* b_ih0 = (const float*)d_in[3];
    const float* b_hh0 = (const float*)d_in[4];
    const float* W_ih1 = (const float*)d_in[5];
    const float* W_hh1 = (const float*)d_in[6];
    const float* b_ih1 = (const float*)d_in[7];
    const float* b_hh1 = (const float*)d_in[8];
    float* out = (float*)d_out;

    // Layer 0 input projection -> g_buf0
    pre0_kernel<<<NEL / 256, 256>>>(x, W_ih0, b_ih0, b_hh0);
    // Layer 0 scan: g_buf0 -> g_buf1
    scan_kernel<<<B, 128>>>(0, W_hh0, out);
    // Layer 1 input projection: g_buf1 -> g_buf0
    proj_kernel<<<PROJ_BLOCKS, 128>>>(W_ih1, b_ih1, b_hh1);
    // Layer 1 scan: g_buf0 -> out
    scan_kernel<<<B, 128>>>(1, W_hh1, out);
}